// round 9
// baseline (speedup 1.0000x reference)
#include <cuda_runtime.h>
#include <cuda_bf16.h>

// Problem constants
#define NTOT 10000
#define BB   4096
#define DD   512

// -------- scratch (device globals; no allocation allowed) --------
__device__ int   g_counts[NTOT];
__device__ int   g_offsets[NTOT];
__device__ int   g_cursor[NTOT];
__device__ int   g_perm[BB];
__device__ int   g_ulist[BB];        // compact sorted unique values (U entries, rest 0)
__device__ int   g_U;
__device__ float g_s[BB];            // per-unique sum of ||y_i||^2
__device__ float g_c[BB];            // per-unique count (float)
__device__ float g_msepart[BB];
__device__ float g_partM[1024];
__device__ float g_partC[1024];
__device__ __align__(16) __nv_bfloat16 g_Zb[(size_t)BB * DD];  // aggregated embeddings

// ================= K0: zero histogram =================
__global__ void k_zero() {
    int i = blockIdx.x * blockDim.x + threadIdx.x;
    if (i < NTOT) g_counts[i] = 0;
}

// ================= K1: histogram of idx =================
__global__ void k_hist(const int* __restrict__ idx) {
    int i = blockIdx.x * blockDim.x + threadIdx.x;
    if (i < BB) atomicAdd(&g_counts[idx[i]], 1);
}

// ====== K2: scans — segment offsets AND compact unique list (1 block) ======
__global__ void k_scan() {
    __shared__ int s[1024];
    int t = threadIdx.x;
    int base = t * 10;
    int c[10];
    int sum = 0, usum = 0;
#pragma unroll
    for (int k = 0; k < 10; k++) {
        int v = (base + k < NTOT) ? g_counts[base + k] : 0;
        c[k] = v; sum += v; usum += (v > 0);
    }
    s[t] = sum;
    __syncthreads();
    for (int off = 1; off < 1024; off <<= 1) {
        int v = (t >= off) ? s[t - off] : 0;
        __syncthreads();
        s[t] += v;
        __syncthreads();
    }
    int run = s[t] - sum;
#pragma unroll
    for (int k = 0; k < 10; k++) {
        if (base + k < NTOT) { g_offsets[base + k] = run; g_cursor[base + k] = run; }
        run += c[k];
    }
    __syncthreads();
    s[t] = usum;
    __syncthreads();
    for (int off = 1; off < 1024; off <<= 1) {
        int v = (t >= off) ? s[t - off] : 0;
        __syncthreads();
        s[t] += v;
        __syncthreads();
    }
    int urun = s[t] - usum;
#pragma unroll
    for (int k = 0; k < 10; k++) {
        if (base + k < NTOT && c[k] > 0) { g_ulist[urun] = base + k; urun++; }
    }
    if (t == 1023) g_U = s[1023];
}

// ================= K3a: atomic scatter =================
__global__ void k_scatter2(const int* __restrict__ idx) {
    int i = blockIdx.x * blockDim.x + threadIdx.x;
    if (i >= BB) return;
    int u = idx[i];
    int pos = atomicAdd(&g_cursor[u], 1);
    g_perm[pos] = i;
}

// ============ K3b: per-value segment sort -> deterministic perm ============
__global__ void k_sortseg() {
    int u = blockIdx.x * blockDim.x + threadIdx.x;
    if (u >= NTOT) return;
    int n = g_counts[u];
    if (n < 2) return;
    int s = g_offsets[u];
    for (int a = 1; a < n; a++) {
        int key = g_perm[s + a];
        int b = a - 1;
        while (b >= 0 && g_perm[s + b] > key) { g_perm[s + b + 1] = g_perm[s + b]; b--; }
        g_perm[s + b + 1] = key;
    }
}

// ===== K4: per-unique aggregation: Z_u (bf16), s_u, c_u, fused MSE =====
__global__ void k_aggr(const float* __restrict__ yp, const float* __restrict__ yt) {
    int k = blockIdx.x;        // 0..BB-1
    int t = threadIdx.x;       // 128 threads, 4 cols each
    int U = g_U;
    __nv_bfloat162* zOut = (__nv_bfloat162*)(g_Zb + (size_t)k * DD);
    if (k >= U) {
        __nv_bfloat162 z2; z2.x = __float2bfloat16(0.f); z2.y = z2.x;
        zOut[2 * t] = z2; zOut[2 * t + 1] = z2;
        if (t == 0) { g_s[k] = 0.f; g_c[k] = 0.f; g_ulist[k] = 0; g_msepart[k] = 0.f; }
        return;
    }
    int u = g_ulist[k];
    int s0 = g_offsets[u], cnt = g_counts[u];
    float ax = 0.f, ay = 0.f, az = 0.f, aw = 0.f, sq = 0.f, ms = 0.f;
    for (int a = 0; a < cnt; a++) {          // ordered -> deterministic
        int i = g_perm[s0 + a];
        float4 v = ((const float4*)(yp + (size_t)i * DD))[t];
        float4 w = ((const float4*)(yt + (size_t)i * DD))[t];
        ax += v.x; ay += v.y; az += v.z; aw += v.w;
        sq += v.x * v.x + v.y * v.y + v.z * v.z + v.w * v.w;
        float dx = v.x - w.x, dy = v.y - w.y, dz = v.z - w.z, dw = v.w - w.w;
        ms += dx * dx + dy * dy + dz * dz + dw * dw;
    }
    zOut[2 * t]     = __floats2bfloat162_rn(ax, ay);
    zOut[2 * t + 1] = __floats2bfloat162_rn(az, aw);
#pragma unroll
    for (int off = 16; off; off >>= 1) {
        sq += __shfl_down_sync(0xffffffffu, sq, off);
        ms += __shfl_down_sync(0xffffffffu, ms, off);
    }
    __shared__ float ssq[4], sms[4];
    int w = t >> 5, l = t & 31;
    if (l == 0) { ssq[w] = sq; sms[w] = ms; }
    __syncthreads();
    if (t == 0) {
        g_s[k] = ssq[0] + ssq[1] + ssq[2] + ssq[3];
        g_c[k] = (float)cnt;
        g_msepart[k] = sms[0] + sms[1] + sms[2] + sms[3];
    }
}

// ==== K5: fused Gram (bf16 mma) + 1-iteration-pipelined register gather ====
#define TM 128
#define TN 128
#define TK 32

// dynamic smem layout (bytes)
#define SA_OFF   0            // 2 stages x 8192
#define SB_OFF   16384        // 2 stages x 8192
#define SM_OFF   32768        // 128 x 136 bf16 = 34816
#define SC_OFF   67584        // 128 x 136 bf16 = 34816
#define SIU_OFF  102400       // 128 int
#define SJU_OFF  102912       // 128 int
#define SSQ_OFF  103424       // 128 float
#define SCC_OFF  103936       // 128 float
#define RED_OFF  104448       // 16 float
#define SMEM_BYTES 104512
#define SMP 68                // sM/sC row pitch in 32-bit words (136 bf16)

__device__ __forceinline__ void ldm_x4(unsigned r[4], unsigned addr) {
    asm volatile("ldmatrix.sync.aligned.m8n8.x4.shared.b16 {%0,%1,%2,%3}, [%4];"
                 : "=r"(r[0]), "=r"(r[1]), "=r"(r[2]), "=r"(r[3])
                 : "r"(addr));
}
__device__ __forceinline__ void mma16816(float c[4], const unsigned a[4],
                                         unsigned b0, unsigned b1) {
    asm volatile(
        "mma.sync.aligned.m16n8k16.row.col.f32.bf16.bf16.f32 "
        "{%0,%1,%2,%3}, {%4,%5,%6,%7}, {%8,%9}, {%0,%1,%2,%3};"
        : "+f"(c[0]), "+f"(c[1]), "+f"(c[2]), "+f"(c[3])
        : "r"(a[0]), "r"(a[1]), "r"(a[2]), "r"(a[3]), "r"(b0), "r"(b1));
}
__device__ __forceinline__ void cp16(unsigned saddr, const void* g) {
    asm volatile("cp.async.cg.shared.global [%0], [%1], 16;" :: "r"(saddr), "l"(g));
}
__device__ __forceinline__ void cp_commit() {
    asm volatile("cp.async.commit_group;");
}
template <int N> __device__ __forceinline__ void cp_wait() {
    asm volatile("cp.async.wait_group %0;" :: "n"(N));
}

__global__ __launch_bounds__(256, 2) void k_main(const float* __restrict__ ML,
                                                 const float* __restrict__ CL) {
    extern __shared__ __align__(16) char dsm[];
    unsigned sbase = (unsigned)__cvta_generic_to_shared(dsm);
    int*      sIu = (int*)(dsm + SIU_OFF);
    int*      sJu = (int*)(dsm + SJU_OFF);
    float*    sSq = (float*)(dsm + SSQ_OFF);
    float*    sCc = (float*)(dsm + SCC_OFF);
    float*    rM  = (float*)(dsm + RED_OFF);
    float*    rC  = rM + 8;
    unsigned* sMu = (unsigned*)(dsm + SM_OFF);   // bf16x2 words, pitch SMP
    unsigned* sCu = (unsigned*)(dsm + SC_OFF);

    int tid = threadIdx.x;
    int Ib = blockIdx.y * TM;
    int Jb = blockIdx.x * TN;
    int bid = blockIdx.y * gridDim.x + blockIdx.x;

    int U = g_U;
    if (Ib >= U || Jb >= U) {                  // tile entirely padding -> zero
        if (tid == 0) { g_partM[bid] = 0.f; g_partC[bid] = 0.f; }
        return;
    }

    if (tid < TM) {
        sIu[tid] = g_ulist[Ib + tid];
        sSq[tid] = g_s[Ib + tid];
    } else {
        sJu[tid - TM] = g_ulist[Jb + tid - TM];
        sCc[tid - TM] = g_c[Jb + tid - TM];
    }
    __syncthreads();                           // indices ready for gather issue

    int wid = tid >> 5, lane = tid & 31;
    int wm = wid & 1;    // 0..1 -> 64 rows each
    int wn = wid >> 1;   // 0..3 -> 32 cols each

    float acc[4][4][4];
#pragma unroll
    for (int a = 0; a < 4; a++)
#pragma unroll
        for (int b = 0; b < 4; b++)
#pragma unroll
            for (int c = 0; c < 4; c++) acc[a][b][c] = 0.f;

    int lr = tid >> 2;  // 0..63
    int lc = tid & 3;   // 16B chunk within 64B row

    auto loadstage = [&](int it, int st) {
        int kk = it * TK;
        unsigned aS = sbase + SA_OFF + st * 8192;
        unsigned bS = sbase + SB_OFF + st * 8192;
#pragma unroll
        for (int h = 0; h < 2; h++) {
            int r = lr + h * 64;
            int pc = lc ^ ((r >> 1) & 3);
            cp16(aS + (unsigned)(r * 4 + pc) * 16u,
                 g_Zb + (size_t)(Ib + r) * DD + kk + lc * 8);
            cp16(bS + (unsigned)(r * 4 + pc) * 16u,
                 g_Zb + (size_t)(Jb + r) * DD + kk + lc * 8);
        }
        cp_commit();
    };

    // register-landed gather: issue slice `it` (rows [8it,8it+8), coalesced cols)
    auto issue_gather = [&](int it, float mv[4], float cv[4]) {
#pragma unroll
        for (int q = 0; q < 2; q++) {
            int p = (it * 2 + q) * 256 + tid;
            int r = p >> 6, c = (p & 63) * 2;
            size_t rowo = (size_t)sIu[r] * NTOT;
            int u0 = sJu[c], u1 = sJu[c + 1];
            mv[2 * q]     = __ldg(ML + rowo + u0);
            mv[2 * q + 1] = __ldg(ML + rowo + u1);
            cv[2 * q]     = __ldg(CL + rowo + u0);
            cv[2 * q + 1] = __ldg(CL + rowo + u1);
        }
    };
    auto stash = [&](int it, const float mv[4], const float cv[4]) {
#pragma unroll
        for (int q = 0; q < 2; q++) {
            int p = (it * 2 + q) * 256 + tid;
            int r = p >> 6, c2 = p & 63;
            __nv_bfloat162 m2 = __floats2bfloat162_rn(mv[2 * q], mv[2 * q + 1]);
            __nv_bfloat162 c2v = __floats2bfloat162_rn(cv[2 * q], cv[2 * q + 1]);
            sMu[r * SMP + c2] = *(unsigned*)&m2;
            sCu[r * SMP + c2] = *(unsigned*)&c2v;
        }
    };

    float curM[4], curC[4];
    issue_gather(0, curM, curC);   // slice 0 in flight through iteration 0
    loadstage(0, 0);

    for (int it = 0; it < 16; it++) {
        int st = it & 1;
        __syncthreads();
        if (it < 15) { loadstage(it + 1, st ^ 1); cp_wait<1>(); }
        else         { cp_wait<0>(); }
        __syncthreads();

        // issue NEXT gather slice now; its values are consumed next iteration
        float nxtM[4], nxtC[4];
        if (it < 15) issue_gather(it + 1, nxtM, nxtC);

        // ---- MMA on stage st ----
        unsigned aBase = sbase + SA_OFF + st * 8192;
        unsigned bBase = sbase + SB_OFF + st * 8192;
#pragma unroll
        for (int ks = 0; ks < 2; ks++) {
            unsigned af[4][4], bf[2][4];
            int chunk = ks * 2 + (lane >> 4);
#pragma unroll
            for (int ma = 0; ma < 4; ma++) {
                int row = wm * 64 + ma * 16 + (lane & 15);
                int pc = chunk ^ ((row >> 1) & 3);
                ldm_x4(af[ma], aBase + (unsigned)(row * 4 + pc) * 16u);
            }
#pragma unroll
            for (int nb = 0; nb < 2; nb++) {
                int row = wn * 32 + nb * 16 + (lane & 15);
                int pc = chunk ^ ((row >> 1) & 3);
                ldm_x4(bf[nb], bBase + (unsigned)(row * 4 + pc) * 16u);
            }
#pragma unroll
            for (int ma = 0; ma < 4; ma++)
#pragma unroll
                for (int na = 0; na < 4; na++) {
                    unsigned b0 = bf[na >> 1][(na & 1)];
                    unsigned b1 = bf[na >> 1][(na & 1) + 2];
                    mma16816(acc[ma][na], af[ma], b0, b1);
                }
        }

        // ---- stash slice `it` (issued one full iteration ago) ----
        stash(it, curM, curC);
#pragma unroll
        for (int k = 0; k < 4; k++) { curM[k] = nxtM[k]; curC[k] = nxtC[k]; }
    }
    __syncthreads();

    // ---- epilogue: d = c_v * s_u - Z_u.Z_v, operands from smem ----
    float aM = 0.f, aC = 0.f;
    int g = lane >> 2, tq = lane & 3;
#pragma unroll
    for (int ma = 0; ma < 4; ma++) {
        int r0 = wm * 64 + ma * 16 + g;
        int r1 = r0 + 8;
        float sq0 = sSq[r0], sq1 = sSq[r1];
#pragma unroll
        for (int na = 0; na < 4; na++) {
            int cw = wn * 16 + na * 4 + tq;   // 32-bit word column (= 2 bf16 cols)
            float cc0 = sCc[2 * cw], cc1 = sCc[2 * cw + 1];
            unsigned wm0 = sMu[r0 * SMP + cw];
            unsigned wm1 = sMu[r1 * SMP + cw];
            unsigned wc0 = sCu[r0 * SMP + cw];
            unsigned wc1 = sCu[r1 * SMP + cw];
            float2 fm0 = __bfloat1622float2(*(__nv_bfloat162*)&wm0);
            float2 fm1 = __bfloat1622float2(*(__nv_bfloat162*)&wm1);
            float2 fc0 = __bfloat1622float2(*(__nv_bfloat162*)&wc0);
            float2 fc1 = __bfloat1622float2(*(__nv_bfloat162*)&wc1);
            float d0 = cc0 * sq0 - acc[ma][na][0];
            float d1 = cc1 * sq0 - acc[ma][na][1];
            float d2 = cc0 * sq1 - acc[ma][na][2];
            float d3 = cc1 * sq1 - acc[ma][na][3];
            aM += fm0.x * d0 + fm0.y * d1 + fm1.x * d2 + fm1.y * d3;
            aC += fc0.x * d0 + fc0.y * d1 + fc1.x * d2 + fc1.y * d3;
        }
    }
#pragma unroll
    for (int off = 16; off; off >>= 1) {
        aM += __shfl_down_sync(0xffffffffu, aM, off);
        aC += __shfl_down_sync(0xffffffffu, aC, off);
    }
    if (lane == 0) { rM[wid] = aM; rC[wid] = aC; }
    __syncthreads();
    if (tid == 0) {
        float tMv = 0.f, tCv = 0.f;
#pragma unroll
        for (int w = 0; w < 8; w++) { tMv += rM[w]; tCv += rC[w]; }
        g_partM[bid] = tMv;
        g_partC[bid] = tCv;
    }
}

// ================= K6: deterministic final reduce =================
__global__ void k_final(float* out, int out_size) {
    int t = threadIdx.x;  // 1024
    double m = (double)g_partM[t];
    double c = (double)g_partC[t];
    double e = 0.0;
#pragma unroll
    for (int k = 0; k < 4; k++) e += (double)g_msepart[t + k * 1024];
#pragma unroll
    for (int off = 16; off; off >>= 1) {
        m += __shfl_down_sync(0xffffffffu, m, off);
        c += __shfl_down_sync(0xffffffffu, c, off);
        e += __shfl_down_sync(0xffffffffu, e, off);
    }
    __shared__ double sm[32], sc[32], se[32];
    int w = t >> 5, l = t & 31;
    if (l == 0) { sm[w] = m; sc[w] = c; se[w] = e; }
    __syncthreads();
    if (t == 0) {
        double M = 0.0, C = 0.0, E = 0.0;
        for (int i = 0; i < 32; i++) { M += sm[i]; C += sc[i]; E += se[i]; }
        double mse = E / ((double)BB * (double)DD);
        double lml = M * 2.0 / ((double)BB * (double)BB);
        double lcl = C * 2.0 / ((double)BB * (double)BB);
        if (out_size > 0) out[0] = (float)(mse + 0.5 * lml - 0.5 * lcl);
        if (out_size > 1) out[1] = (float)lml;
        if (out_size > 2) out[2] = (float)lcl;
    }
}

// ================= launch =================
extern "C" void kernel_launch(void* const* d_in, const int* in_sizes, int n_in,
                              void* d_out, int out_size) {
    const float* yp = (const float*)d_in[0];
    const float* yt = (const float*)d_in[1];
    const int*   ix = (const int*)d_in[2];
    const float* ml = (const float*)d_in[3];
    const float* cl = (const float*)d_in[4];
    (void)in_sizes; (void)n_in;

    static bool attr_set = false;
    if (!attr_set) {
        cudaFuncSetAttribute(k_main, cudaFuncAttributeMaxDynamicSharedMemorySize,
                             SMEM_BYTES);
        attr_set = true;
    }

    k_zero<<<(NTOT + 255) / 256, 256>>>();
    k_hist<<<BB / 256, 256>>>(ix);
    k_scan<<<1, 1024>>>();
    k_scatter2<<<BB / 256, 256>>>(ix);
    k_sortseg<<<(NTOT + 255) / 256, 256>>>();
    k_aggr<<<BB, 128>>>(yp, yt);
    k_main<<<dim3(BB / TN, BB / TM), 256, SMEM_BYTES>>>(ml, cl);
    k_final<<<1, 1024>>>((float*)d_out, out_size);
}

// round 10
// speedup vs baseline: 1.0851x; 1.0851x over previous
#include <cuda_runtime.h>
#include <cuda_bf16.h>

// Problem constants
#define NTOT 10000
#define BB   4096
#define DD   512

// -------- scratch (device globals; no allocation allowed) --------
__device__ int   g_counts[NTOT];
__device__ int   g_offsets[NTOT];
__device__ int   g_perm[BB];
__device__ int   g_ulist[BB];        // compact sorted unique values (U entries)
__device__ int   g_U;
__device__ float g_s[BB];            // per-unique sum of ||y_i||^2
__device__ float g_c[BB];            // per-unique count (float)
__device__ float g_msepart[BB];
__device__ float g_partM[1024];
__device__ float g_partC[1024];
__device__ __align__(16) __nv_bfloat16 g_Zb[(size_t)BB * DD];  // aggregated embeddings

// ========== K1: fused preprocessing (single block, all state in smem) ==========
// zero-hist -> histogram -> dual scan (offsets + unique compaction) -> atomic
// scatter -> per-segment insertion sort. One block => __syncthreads ordering.
__global__ __launch_bounds__(1024, 1) void k_prep(const int* __restrict__ idx) {
    __shared__ int scnt[NTOT];     // counts, then reused as scatter cursors
    __shared__ int sscan[1024];
    __shared__ int sidx[BB];
    int t = threadIdx.x;

    // zero counts
#pragma unroll
    for (int k = 0; k < 10; k++) {
        int i = t + k * 1024;
        if (i < NTOT) scnt[i] = 0;
    }
    // cache idx
#pragma unroll
    for (int k = 0; k < 4; k++) sidx[t + k * 1024] = idx[t + k * 1024];
    __syncthreads();

    // histogram (smem atomics)
#pragma unroll
    for (int k = 0; k < 4; k++) atomicAdd(&scnt[sidx[t + k * 1024]], 1);
    __syncthreads();

    // chunked scan: each thread owns 10 consecutive values
    int base = t * 10;
    int c[10];
    int sum = 0, usum = 0;
#pragma unroll
    for (int k = 0; k < 10; k++) {
        int v = (base + k < NTOT) ? scnt[base + k] : 0;
        c[k] = v; sum += v; usum += (v > 0);
    }
    // scan 1: position offsets
    sscan[t] = sum;
    __syncthreads();
    for (int off = 1; off < 1024; off <<= 1) {
        int v = (t >= off) ? sscan[t - off] : 0;
        __syncthreads();
        sscan[t] += v;
        __syncthreads();
    }
    int run = sscan[t] - sum;
    int offs[10];
#pragma unroll
    for (int k = 0; k < 10; k++) {
        offs[k] = run;
        if (base + k < NTOT) {
            g_offsets[base + k] = run;
            g_counts[base + k]  = c[k];
        }
        run += c[k];
    }
    __syncthreads();
    // scan 2: unique compaction
    sscan[t] = usum;
    __syncthreads();
    for (int off = 1; off < 1024; off <<= 1) {
        int v = (t >= off) ? sscan[t - off] : 0;
        __syncthreads();
        sscan[t] += v;
        __syncthreads();
    }
    int urun = sscan[t] - usum;
#pragma unroll
    for (int k = 0; k < 10; k++) {
        if (base + k < NTOT && c[k] > 0) { g_ulist[urun] = base + k; urun++; }
    }
    if (t == 1023) g_U = sscan[1023];
    __syncthreads();

    // reuse scnt as cursors (= offsets)
#pragma unroll
    for (int k = 0; k < 10; k++)
        if (base + k < NTOT) scnt[base + k] = offs[k];
    __syncthreads();

    // atomic scatter (smem cursors)
#pragma unroll
    for (int k = 0; k < 4; k++) {
        int i = t + k * 1024;
        int u = sidx[i];
        int pos = atomicAdd(&scnt[u], 1);
        g_perm[pos] = i;
    }
    __syncthreads();

    // per-segment insertion sort -> deterministic permutation
#pragma unroll
    for (int k = 0; k < 10; k++) {
        int u = base + k;
        if (u >= NTOT) continue;
        int n = c[k];
        if (n < 2) continue;
        int s0 = offs[k];
        for (int a = 1; a < n; a++) {
            int key = g_perm[s0 + a];
            int b = a - 1;
            while (b >= 0 && g_perm[s0 + b] > key) {
                g_perm[s0 + b + 1] = g_perm[s0 + b];
                b--;
            }
            g_perm[s0 + b + 1] = key;
        }
    }
}

// ===== K2: per-unique aggregation: Z_u (bf16), s_u, c_u, fused MSE =====
__global__ void k_aggr(const float* __restrict__ yp, const float* __restrict__ yt) {
    int k = blockIdx.x;        // 0..BB-1
    int t = threadIdx.x;       // 128 threads, 4 cols each
    int U = g_U;
    __nv_bfloat162* zOut = (__nv_bfloat162*)(g_Zb + (size_t)k * DD);
    if (k >= U) {
        __nv_bfloat162 z2; z2.x = __float2bfloat16(0.f); z2.y = z2.x;
        zOut[2 * t] = z2; zOut[2 * t + 1] = z2;
        if (t == 0) { g_s[k] = 0.f; g_c[k] = 0.f; g_ulist[k] = 0; g_msepart[k] = 0.f; }
        return;
    }
    int u = g_ulist[k];
    int s0 = g_offsets[u], cnt = g_counts[u];
    float ax = 0.f, ay = 0.f, az = 0.f, aw = 0.f, sq = 0.f, ms = 0.f;
    for (int a = 0; a < cnt; a++) {          // ordered -> deterministic
        int i = g_perm[s0 + a];
        float4 v = ((const float4*)(yp + (size_t)i * DD))[t];
        float4 w = ((const float4*)(yt + (size_t)i * DD))[t];
        ax += v.x; ay += v.y; az += v.z; aw += v.w;
        sq += v.x * v.x + v.y * v.y + v.z * v.z + v.w * v.w;
        float dx = v.x - w.x, dy = v.y - w.y, dz = v.z - w.z, dw = v.w - w.w;
        ms += dx * dx + dy * dy + dz * dz + dw * dw;
    }
    zOut[2 * t]     = __floats2bfloat162_rn(ax, ay);
    zOut[2 * t + 1] = __floats2bfloat162_rn(az, aw);
#pragma unroll
    for (int off = 16; off; off >>= 1) {
        sq += __shfl_down_sync(0xffffffffu, sq, off);
        ms += __shfl_down_sync(0xffffffffu, ms, off);
    }
    __shared__ float ssq[4], sms[4];
    int w = t >> 5, l = t & 31;
    if (l == 0) { ssq[w] = sq; sms[w] = ms; }
    __syncthreads();
    if (t == 0) {
        g_s[k] = ssq[0] + ssq[1] + ssq[2] + ssq[3];
        g_c[k] = (float)cnt;
        g_msepart[k] = sms[0] + sms[1] + sms[2] + sms[3];
    }
}

// ======= K3: fused Gram (bf16 mma) + pipelined coalesced gather (R6 proven) =======
#define TM 128
#define TN 128
#define TK 32

// dynamic smem layout (bytes)
#define SA_OFF   0            // 2 stages x 8192
#define SB_OFF   16384        // 2 stages x 8192
#define SM_OFF   32768        // 128 x 136 bf16 = 34816
#define SC_OFF   67584        // 128 x 136 bf16 = 34816
#define SIU_OFF  102400       // 128 int
#define SJU_OFF  102912       // 128 int
#define SSQ_OFF  103424       // 128 float
#define SCC_OFF  103936       // 128 float
#define RED_OFF  104448       // 16 float
#define SMEM_BYTES 104512
#define SMP 68                // sM/sC row pitch in 32-bit words (136 bf16)

__device__ __forceinline__ void ldm_x4(unsigned r[4], unsigned addr) {
    asm volatile("ldmatrix.sync.aligned.m8n8.x4.shared.b16 {%0,%1,%2,%3}, [%4];"
                 : "=r"(r[0]), "=r"(r[1]), "=r"(r[2]), "=r"(r[3])
                 : "r"(addr));
}
__device__ __forceinline__ void mma16816(float c[4], const unsigned a[4],
                                         unsigned b0, unsigned b1) {
    asm volatile(
        "mma.sync.aligned.m16n8k16.row.col.f32.bf16.bf16.f32 "
        "{%0,%1,%2,%3}, {%4,%5,%6,%7}, {%8,%9}, {%0,%1,%2,%3};"
        : "+f"(c[0]), "+f"(c[1]), "+f"(c[2]), "+f"(c[3])
        : "r"(a[0]), "r"(a[1]), "r"(a[2]), "r"(a[3]), "r"(b0), "r"(b1));
}
__device__ __forceinline__ void cp16(unsigned saddr, const void* g) {
    asm volatile("cp.async.cg.shared.global [%0], [%1], 16;" :: "r"(saddr), "l"(g));
}
__device__ __forceinline__ void cp_commit() {
    asm volatile("cp.async.commit_group;");
}
template <int N> __device__ __forceinline__ void cp_wait() {
    asm volatile("cp.async.wait_group %0;" :: "n"(N));
}

__global__ __launch_bounds__(256, 2) void k_main(const float* __restrict__ ML,
                                                 const float* __restrict__ CL) {
    extern __shared__ __align__(16) char dsm[];
    unsigned sbase = (unsigned)__cvta_generic_to_shared(dsm);
    int*      sIu = (int*)(dsm + SIU_OFF);
    int*      sJu = (int*)(dsm + SJU_OFF);
    float*    sSq = (float*)(dsm + SSQ_OFF);
    float*    sCc = (float*)(dsm + SCC_OFF);
    float*    rM  = (float*)(dsm + RED_OFF);
    float*    rC  = rM + 8;
    unsigned* sMu = (unsigned*)(dsm + SM_OFF);   // bf16x2 words, pitch SMP
    unsigned* sCu = (unsigned*)(dsm + SC_OFF);

    int tid = threadIdx.x;
    int Ib = blockIdx.y * TM;
    int Jb = blockIdx.x * TN;
    int bid = blockIdx.y * gridDim.x + blockIdx.x;

    int U = g_U;
    if (Ib >= U || Jb >= U) {                  // tile entirely padding -> zero
        if (tid == 0) { g_partM[bid] = 0.f; g_partC[bid] = 0.f; }
        return;
    }

    if (tid < TM) {
        sIu[tid] = g_ulist[Ib + tid];
        sSq[tid] = g_s[Ib + tid];
    } else {
        sJu[tid - TM] = g_ulist[Jb + tid - TM];
        sCc[tid - TM] = g_c[Jb + tid - TM];
    }

    int wid = tid >> 5, lane = tid & 31;
    int wm = wid & 1;    // 0..1 -> 64 rows each
    int wn = wid >> 1;   // 0..3 -> 32 cols each

    float acc[4][4][4];
#pragma unroll
    for (int a = 0; a < 4; a++)
#pragma unroll
        for (int b = 0; b < 4; b++)
#pragma unroll
            for (int c = 0; c < 4; c++) acc[a][b][c] = 0.f;

    int lr = tid >> 2;  // 0..63
    int lc = tid & 3;   // 16B chunk within 64B row

    auto loadstage = [&](int it, int st) {
        int kk = it * TK;
        unsigned aS = sbase + SA_OFF + st * 8192;
        unsigned bS = sbase + SB_OFF + st * 8192;
#pragma unroll
        for (int h = 0; h < 2; h++) {
            int r = lr + h * 64;
            int pc = lc ^ ((r >> 1) & 3);
            cp16(aS + (unsigned)(r * 4 + pc) * 16u,
                 g_Zb + (size_t)(Ib + r) * DD + kk + lc * 8);
            cp16(bS + (unsigned)(r * 4 + pc) * 16u,
                 g_Zb + (size_t)(Jb + r) * DD + kk + lc * 8);
        }
        cp_commit();
    };

    loadstage(0, 0);

    for (int it = 0; it < 16; it++) {
        int st = it & 1;
        __syncthreads();
        if (it < 15) { loadstage(it + 1, st ^ 1); cp_wait<1>(); }
        else         { cp_wait<0>(); }
        __syncthreads();

        // ---- issue gather loads (coalesced: lanes = consecutive sorted cols) ----
        float mv[4], cv[4];
        int gr[2], gc[2];
#pragma unroll
        for (int q = 0; q < 2; q++) {
            int p = (it * 2 + q) * 256 + tid;
            int r = p >> 6, c2 = p & 63, c = c2 * 2;
            gr[q] = r; gc[q] = c2;
            size_t rowo = (size_t)sIu[r] * NTOT;
            int u0 = sJu[c], u1 = sJu[c + 1];
            mv[2 * q]     = __ldg(ML + rowo + u0);
            mv[2 * q + 1] = __ldg(ML + rowo + u1);
            cv[2 * q]     = __ldg(CL + rowo + u0);
            cv[2 * q + 1] = __ldg(CL + rowo + u1);
        }

        // ---- MMA on stage st (gather loads in flight) ----
        unsigned aBase = sbase + SA_OFF + st * 8192;
        unsigned bBase = sbase + SB_OFF + st * 8192;
#pragma unroll
        for (int ks = 0; ks < 2; ks++) {
            unsigned af[4][4], bf[2][4];
            int chunk = ks * 2 + (lane >> 4);
#pragma unroll
            for (int ma = 0; ma < 4; ma++) {
                int row = wm * 64 + ma * 16 + (lane & 15);
                int pc = chunk ^ ((row >> 1) & 3);
                ldm_x4(af[ma], aBase + (unsigned)(row * 4 + pc) * 16u);
            }
#pragma unroll
            for (int nb = 0; nb < 2; nb++) {
                int row = wn * 32 + nb * 16 + (lane & 15);
                int pc = chunk ^ ((row >> 1) & 3);
                ldm_x4(bf[nb], bBase + (unsigned)(row * 4 + pc) * 16u);
            }
#pragma unroll
            for (int ma = 0; ma < 4; ma++)
#pragma unroll
                for (int na = 0; na < 4; na++) {
                    unsigned b0 = bf[na >> 1][(na & 1)];
                    unsigned b1 = bf[na >> 1][(na & 1) + 2];
                    mma16816(acc[ma][na], af[ma], b0, b1);
                }
        }

        // ---- stash gathered values (arrived during MMA) ----
#pragma unroll
        for (int q = 0; q < 2; q++) {
            __nv_bfloat162 m2 = __floats2bfloat162_rn(mv[2 * q], mv[2 * q + 1]);
            __nv_bfloat162 c2 = __floats2bfloat162_rn(cv[2 * q], cv[2 * q + 1]);
            sMu[gr[q] * SMP + gc[q]] = *(unsigned*)&m2;
            sCu[gr[q] * SMP + gc[q]] = *(unsigned*)&c2;
        }
    }
    __syncthreads();

    // ---- epilogue: d = c_v * s_u - Z_u.Z_v, operands from smem ----
    float aM = 0.f, aC = 0.f;
    int g = lane >> 2, tq = lane & 3;
#pragma unroll
    for (int ma = 0; ma < 4; ma++) {
        int r0 = wm * 64 + ma * 16 + g;
        int r1 = r0 + 8;
        float sq0 = sSq[r0], sq1 = sSq[r1];
#pragma unroll
        for (int na = 0; na < 4; na++) {
            int cw = wn * 16 + na * 4 + tq;   // 32-bit word column (= 2 bf16 cols)
            float cc0 = sCc[2 * cw], cc1 = sCc[2 * cw + 1];
            unsigned wm0 = sMu[r0 * SMP + cw];
            unsigned wm1 = sMu[r1 * SMP + cw];
            unsigned wc0 = sCu[r0 * SMP + cw];
            unsigned wc1 = sCu[r1 * SMP + cw];
            float2 fm0 = __bfloat1622float2(*(__nv_bfloat162*)&wm0);
            float2 fm1 = __bfloat1622float2(*(__nv_bfloat162*)&wm1);
            float2 fc0 = __bfloat1622float2(*(__nv_bfloat162*)&wc0);
            float2 fc1 = __bfloat1622float2(*(__nv_bfloat162*)&wc1);
            float d0 = cc0 * sq0 - acc[ma][na][0];
            float d1 = cc1 * sq0 - acc[ma][na][1];
            float d2 = cc0 * sq1 - acc[ma][na][2];
            float d3 = cc1 * sq1 - acc[ma][na][3];
            aM += fm0.x * d0 + fm0.y * d1 + fm1.x * d2 + fm1.y * d3;
            aC += fc0.x * d0 + fc0.y * d1 + fc1.x * d2 + fc1.y * d3;
        }
    }
#pragma unroll
    for (int off = 16; off; off >>= 1) {
        aM += __shfl_down_sync(0xffffffffu, aM, off);
        aC += __shfl_down_sync(0xffffffffu, aC, off);
    }
    if (lane == 0) { rM[wid] = aM; rC[wid] = aC; }
    __syncthreads();
    if (tid == 0) {
        float tMv = 0.f, tCv = 0.f;
#pragma unroll
        for (int w = 0; w < 8; w++) { tMv += rM[w]; tCv += rC[w]; }
        g_partM[bid] = tMv;
        g_partC[bid] = tCv;
    }
}

// ================= K4: deterministic final reduce =================
__global__ void k_final(float* out, int out_size) {
    int t = threadIdx.x;  // 1024
    double m = (double)g_partM[t];
    double c = (double)g_partC[t];
    double e = 0.0;
#pragma unroll
    for (int k = 0; k < 4; k++) e += (double)g_msepart[t + k * 1024];
#pragma unroll
    for (int off = 16; off; off >>= 1) {
        m += __shfl_down_sync(0xffffffffu, m, off);
        c += __shfl_down_sync(0xffffffffu, c, off);
        e += __shfl_down_sync(0xffffffffu, e, off);
    }
    __shared__ double sm[32], sc[32], se[32];
    int w = t >> 5, l = t & 31;
    if (l == 0) { sm[w] = m; sc[w] = c; se[w] = e; }
    __syncthreads();
    if (t == 0) {
        double M = 0.0, C = 0.0, E = 0.0;
        for (int i = 0; i < 32; i++) { M += sm[i]; C += sc[i]; E += se[i]; }
        double mse = E / ((double)BB * (double)DD);
        double lml = M * 2.0 / ((double)BB * (double)BB);
        double lcl = C * 2.0 / ((double)BB * (double)BB);
        if (out_size > 0) out[0] = (float)(mse + 0.5 * lml - 0.5 * lcl);
        if (out_size > 1) out[1] = (float)lml;
        if (out_size > 2) out[2] = (float)lcl;
    }
}

// ================= launch =================
extern "C" void kernel_launch(void* const* d_in, const int* in_sizes, int n_in,
                              void* d_out, int out_size) {
    const float* yp = (const float*)d_in[0];
    const float* yt = (const float*)d_in[1];
    const int*   ix = (const int*)d_in[2];
    const float* ml = (const float*)d_in[3];
    const float* cl = (const float*)d_in[4];
    (void)in_sizes; (void)n_in;

    static bool attr_set = false;
    if (!attr_set) {
        cudaFuncSetAttribute(k_main, cudaFuncAttributeMaxDynamicSharedMemorySize,
                             SMEM_BYTES);
        attr_set = true;
    }

    k_prep<<<1, 1024>>>(ix);
    k_aggr<<<BB, 128>>>(yp, yt);
    k_main<<<dim3(BB / TN, BB / TM), 256, SMEM_BYTES>>>(ml, cl);
    k_final<<<1, 1024>>>((float*)d_out, out_size);
}